// round 1
// baseline (speedup 1.0000x reference)
#include <cuda_runtime.h>
#include <cuda_bf16.h>
#include <cstdint>

// ---------------- problem constants ----------------
#define MAX_N 100000
#define MAX_E 1700000
#define F_IN  256
#define F_MID 128
#define F_OUT 64

// ---------------- device scratch (no allocations allowed) ----------------
__device__ int   g_deg[MAX_N];
__device__ float g_dis[MAX_N];          // d^-1/2
__device__ int   g_rowptr[MAX_N + 1];
__device__ int   g_cursor[MAX_N];
__device__ int   g_bsum[128];
__device__ int   g_col[MAX_E];
__device__ float g_w[MAX_E];
__device__ float g_XW1[(size_t)MAX_N * F_MID];  // 51.2 MB
__device__ float g_H[(size_t)MAX_N * F_MID];    // 51.2 MB
__device__ float g_HW2[(size_t)MAX_N * F_OUT];  // 25.6 MB

// ---------------- degree / normalization ----------------
__global__ void k_zero_deg(int n) {
    int i = blockIdx.x * blockDim.x + threadIdx.x;
    if (i < n) g_deg[i] = 0;
}

__global__ void k_count(const int* __restrict__ erow, int E) {
    int e = blockIdx.x * blockDim.x + threadIdx.x;
    if (e < E) atomicAdd(&g_deg[erow[e]], 1);
}

__global__ void k_dis(int n) {
    int i = blockIdx.x * blockDim.x + threadIdx.x;
    if (i < n) g_dis[i] = rsqrtf((float)g_deg[i]);   // deg >= 1 (self-loops)
}

// ---------------- exclusive scan of g_deg -> g_rowptr ----------------
__global__ void k_scan_part(int n) {
    __shared__ int s[1024];
    int i = blockIdx.x * 1024 + threadIdx.x;
    s[threadIdx.x] = (i < n) ? g_deg[i] : 0;
    __syncthreads();
    for (int off = 512; off > 0; off >>= 1) {
        if (threadIdx.x < off) s[threadIdx.x] += s[threadIdx.x + off];
        __syncthreads();
    }
    if (threadIdx.x == 0) g_bsum[blockIdx.x] = s[0];
}

__global__ void k_scan_bsums(int nb, int n) {
    if (threadIdx.x == 0 && blockIdx.x == 0) {
        int run = 0;
        for (int b = 0; b < nb; b++) {
            int t = g_bsum[b];
            g_bsum[b] = run;
            run += t;
        }
        g_rowptr[n] = run;
    }
}

__global__ void k_scan_final(int n) {
    __shared__ int s[1024];
    int i = blockIdx.x * 1024 + threadIdx.x;
    int v = (i < n) ? g_deg[i] : 0;
    s[threadIdx.x] = v;
    __syncthreads();
    // Hillis-Steele inclusive scan
    for (int off = 1; off < 1024; off <<= 1) {
        int t = (threadIdx.x >= off) ? s[threadIdx.x - off] : 0;
        __syncthreads();
        s[threadIdx.x] += t;
        __syncthreads();
    }
    if (i < n) {
        int excl = s[threadIdx.x] - v + g_bsum[blockIdx.x];
        g_rowptr[i] = excl;
        g_cursor[i] = excl;
    }
}

// ---------------- scatter into CSR ----------------
__global__ void k_scatter(const int* __restrict__ erow,
                          const int* __restrict__ ecol, int E) {
    int e = blockIdx.x * blockDim.x + threadIdx.x;
    if (e < E) {
        int r = erow[e];
        int c = ecol[e];
        int p = atomicAdd(&g_cursor[r], 1);
        g_col[p] = c;
        g_w[p]   = g_dis[r] * g_dis[c];
    }
}

// ---------------- tiled SGEMM: C[M,BN] = A[M,K] @ B[K,BN], N == BN ----------------
template<int BN, int TN>
__global__ __launch_bounds__(256)
void sgemm(int M, int K,
           const float* __restrict__ A, const float* __restrict__ B,
           float* __restrict__ C) {
    constexpr int BM = 128, BK = 16, TM = 8;
    constexpr int NTH = (BM / TM) * (BN / TN);   // 256
    __shared__ float As[BK][BM + 4];
    __shared__ float Bs[BK][BN];

    const int tid = threadIdx.x;
    const int tx = tid % (BN / TN);
    const int ty = tid / (BN / TN);
    const int rowBase = blockIdx.y * BM;

    float acc[TM][TN];
#pragma unroll
    for (int i = 0; i < TM; i++)
#pragma unroll
        for (int j = 0; j < TN; j++) acc[i][j] = 0.f;

    constexpr int AVECS = BM * BK / 4;
    constexpr int BVECS = BK * BN / 4;

    for (int k0 = 0; k0 < K; k0 += BK) {
#pragma unroll
        for (int v = tid; v < AVECS; v += NTH) {
            int r  = v / (BK / 4);
            int kv = v % (BK / 4);
            float4 a = make_float4(0.f, 0.f, 0.f, 0.f);
            int gr = rowBase + r;
            if (gr < M) a = *(const float4*)&A[(size_t)gr * K + k0 + kv * 4];
            As[kv * 4 + 0][r] = a.x;
            As[kv * 4 + 1][r] = a.y;
            As[kv * 4 + 2][r] = a.z;
            As[kv * 4 + 3][r] = a.w;
        }
#pragma unroll
        for (int v = tid; v < BVECS; v += NTH) {
            int kk = v / (BN / 4);
            int nv = v % (BN / 4);
            *(float4*)&Bs[kk][nv * 4] =
                *(const float4*)&B[(size_t)(k0 + kk) * BN + nv * 4];
        }
        __syncthreads();

#pragma unroll
        for (int k = 0; k < BK; k++) {
            float ra[TM], rb[TN];
#pragma unroll
            for (int i = 0; i < TM; i++) ra[i] = As[k][ty * TM + i];
#pragma unroll
            for (int j = 0; j < TN; j++) rb[j] = Bs[k][tx * TN + j];
#pragma unroll
            for (int i = 0; i < TM; i++)
#pragma unroll
                for (int j = 0; j < TN; j++) acc[i][j] += ra[i] * rb[j];
        }
        __syncthreads();
    }

#pragma unroll
    for (int i = 0; i < TM; i++) {
        int gr = rowBase + ty * TM + i;
        if (gr < M) {
#pragma unroll
            for (int j = 0; j < TN; j += 4) {
                float4 o = make_float4(acc[i][j], acc[i][j + 1],
                                       acc[i][j + 2], acc[i][j + 3]);
                *(float4*)&C[(size_t)gr * BN + tx * TN + j] = o;
            }
        }
    }
}

// ---------------- SPMM: warp per row, 128 cols (float4/lane), relu ----------------
__global__ __launch_bounds__(256)
void k_spmm128_relu(const float* __restrict__ Xin, float* __restrict__ Yout, int n) {
    int warp = (blockIdx.x * blockDim.x + threadIdx.x) >> 5;
    if (warp >= n) return;
    int lane = threadIdx.x & 31;
    int s = g_rowptr[warp];
    int e = g_rowptr[warp + 1];
    const float4* base = (const float4*)Xin;   // row stride = 32 float4
    float4 acc = make_float4(0.f, 0.f, 0.f, 0.f);
    int i = s;
    for (; i + 1 < e; i += 2) {
        int   c0 = __ldg(&g_col[i]);
        int   c1 = __ldg(&g_col[i + 1]);
        float w0 = __ldg(&g_w[i]);
        float w1 = __ldg(&g_w[i + 1]);
        float4 v0 = __ldg(&base[(size_t)c0 * 32 + lane]);
        float4 v1 = __ldg(&base[(size_t)c1 * 32 + lane]);
        acc.x += w0 * v0.x + w1 * v1.x;
        acc.y += w0 * v0.y + w1 * v1.y;
        acc.z += w0 * v0.z + w1 * v1.z;
        acc.w += w0 * v0.w + w1 * v1.w;
    }
    if (i < e) {
        int   c0 = __ldg(&g_col[i]);
        float w0 = __ldg(&g_w[i]);
        float4 v0 = __ldg(&base[(size_t)c0 * 32 + lane]);
        acc.x += w0 * v0.x; acc.y += w0 * v0.y;
        acc.z += w0 * v0.z; acc.w += w0 * v0.w;
    }
    acc.x = fmaxf(acc.x, 0.f);
    acc.y = fmaxf(acc.y, 0.f);
    acc.z = fmaxf(acc.z, 0.f);
    acc.w = fmaxf(acc.w, 0.f);
    ((float4*)Yout)[(size_t)warp * 32 + lane] = acc;
}

// ---------------- SPMM: warp per row, 64 cols (float2/lane), no relu ----------------
__global__ __launch_bounds__(256)
void k_spmm64(const float* __restrict__ Xin, float* __restrict__ Yout, int n) {
    int warp = (blockIdx.x * blockDim.x + threadIdx.x) >> 5;
    if (warp >= n) return;
    int lane = threadIdx.x & 31;
    int s = g_rowptr[warp];
    int e = g_rowptr[warp + 1];
    const float2* base = (const float2*)Xin;   // row stride = 32 float2
    float2 acc = make_float2(0.f, 0.f);
    int i = s;
    for (; i + 1 < e; i += 2) {
        int   c0 = __ldg(&g_col[i]);
        int   c1 = __ldg(&g_col[i + 1]);
        float w0 = __ldg(&g_w[i]);
        float w1 = __ldg(&g_w[i + 1]);
        float2 v0 = __ldg(&base[(size_t)c0 * 32 + lane]);
        float2 v1 = __ldg(&base[(size_t)c1 * 32 + lane]);
        acc.x += w0 * v0.x + w1 * v1.x;
        acc.y += w0 * v0.y + w1 * v1.y;
    }
    if (i < e) {
        int   c0 = __ldg(&g_col[i]);
        float w0 = __ldg(&g_w[i]);
        float2 v0 = __ldg(&base[(size_t)c0 * 32 + lane]);
        acc.x += w0 * v0.x;
        acc.y += w0 * v0.y;
    }
    ((float2*)Yout)[(size_t)warp * 32 + lane] = acc;
}

// ---------------- launch ----------------
extern "C" void kernel_launch(void* const* d_in, const int* in_sizes, int n_in,
                              void* d_out, int out_size) {
    const float* X  = (const float*)d_in[0];
    const float* W1 = (const float*)d_in[1];
    const float* W2 = (const float*)d_in[2];
    const int* erow = (const int*)d_in[3];
    const int* ecol = (const int*)d_in[4];
    const int E = in_sizes[3];
    const int n = in_sizes[0] / F_IN;
    float* out = (float*)d_out;

    const int NB = (n + 1023) / 1024;          // 98 scan blocks

    // CSR build
    k_zero_deg<<<NB, 1024>>>(n);
    k_count<<<(E + 255) / 256, 256>>>(erow, E);
    k_dis<<<NB, 1024>>>(n);
    k_scan_part<<<NB, 1024>>>(n);
    k_scan_bsums<<<1, 32>>>(NB, n);
    k_scan_final<<<NB, 1024>>>(n);
    k_scatter<<<(E + 255) / 256, 256>>>(erow, ecol, E);

    // layer 1: XW1 = X @ W1 ; H = relu(Ahat @ XW1)
    {
        dim3 grid(1, (n + 127) / 128);
        sgemm<128, 8><<<grid, 256>>>(n, F_IN, X, W1, g_XW1);
    }
    {
        // warp per row
        int nwarp_threads = n * 32;
        k_spmm128_relu<<<(nwarp_threads + 255) / 256, 256>>>(g_XW1, g_H, n);
    }

    // layer 2: HW2 = H @ W2 ; out = Ahat @ HW2
    {
        dim3 grid(1, (n + 127) / 128);
        sgemm<64, 4><<<grid, 256>>>(n, F_MID, g_H, W2, g_HW2);
    }
    {
        int nwarp_threads = n * 32;
        k_spmm64<<<(nwarp_threads + 255) / 256, 256>>>(g_HW2, out, n);
    }
}